// round 16
// baseline (speedup 1.0000x reference)
#include <cuda_runtime.h>
#include <cstdint>

// ============================================================================
// GRU_Att_Layer R16: R13 + XN prefetch hoisted under dot1.
//  - x(t+1) LDG/STS into XN issues at step start (hidden under dot1's
//    LDS/FMA phase) instead of inside the barA window
//  - tiny XV[16][18] buffer preserves own x(t) rows for the combine
//  - barA window now empty (arrive -> wait); barB window = out STG + A1x
//  - otherwise exactly R13: flag barriers, dot8w, classic launch
// B=128,S=1024,I=256,H=256. 128 CTAs: g=blockIdx&15 rows, p=blockIdx>>4.
// 512 threads.
// ============================================================================

#define S_LEN 1024
#define NBLK  128
#define NTHR  512

#define ZSTR  20
#define W1STR 20
#define W2STR 52
#define WCSTR 52
#define PBS   20
#define XVS   18

// SMEM layout (float offsets)
#define OFF_W1   0                        // [512][20] W_att^T (16 rows)
#define OFF_W2   (OFF_W1 + 512*W1STR)     // 10240 [256][52] w_hh^T triples
#define OFF_WC   (OFF_W2 + 256*W2STR)     // 23552 [256][52] w_ih^T triples
#define OFF_Z    (OFF_WC + 256*WCSTR)     // 36864 [512][20]: [xg ; h]^T
#define OFF_XN   (OFF_Z  + 512*ZSTR)      // 47104 [256][20] x(t or t+1)^T
#define OFF_PB2  (OFF_XN + 256*ZSTR)      // 52224 [2][48][20] gh partials
#define OFF_PB1H (OFF_PB2 + 2*48*PBS)     // 54144 [2][16][20]
#define OFF_PB1X (OFF_PB1H + 2*16*PBS)    // 54784 [2][16][20]
#define OFF_PBC  (OFF_PB1X + 2*16*PBS)    // 55424 [2][48][20]
#define OFF_BA   (OFF_PBC + 2*48*PBS)     // 57344
#define OFF_BHH  (OFF_BA + 16)
#define OFF_BIH  (OFF_BHH + 48)
#define OFF_BASE (OFF_BIH + 48)           // 57456: 16 flag bases
#define OFF_XV   (OFF_BASE + 16)          // 57472: [16][18] own x(t) rows
#define SMEM_FLOATS (OFF_XV + 16*XVS)     // 57760
#define SMEM_BYTES  (SMEM_FLOATS * 4)     // 231040 B (< 232448 opt-in max)

// ---------------- scratch (device globals; allocation forbidden) -----------
// transposed: [pgroup][k 0..255][bb 0..15]
__device__ __align__(16) float g_hT [8 * 256 * 16];
__device__ __align__(16) float g_xgT[8 * 256 * 16];
__device__ unsigned g_flag[NBLK * 32];   // per-CTA epoch, own sector

// ---------------- split flag barrier: arrive / wait -------------------------
__device__ __forceinline__ void pbar_arrive(const unsigned* base_sm, int g,
                                            unsigned n) {
    __syncthreads();                       // CTA's phase stores issued
    if (threadIdx.x == 0) {
        __threadfence();                   // publish them
        *(volatile unsigned*)&g_flag[blockIdx.x * 32] = base_sm[g] + n;
    }
}
__device__ __forceinline__ void pbar_wait(const unsigned* base_sm, int p,
                                          unsigned n) {
    if (threadIdx.x < 16) {
        volatile unsigned* f = &g_flag[(p * 16 + threadIdx.x) * 32];
        unsigned tgt = base_sm[threadIdx.x] + n;
        while ((int)(*f - tgt) < 0) { }
        __threadfence();                   // acquire
    }
    __syncthreads();
}

__device__ __forceinline__ float sigmoidf_(float x) {
    return 1.0f / (1.0f + __expf(-x));
}
__device__ __forceinline__ uint32_t sm_u32(const void* ptr) {
    uint32_t a;
    asm("{ .reg .u64 t; cvta.to.shared.u64 t, %1; cvt.u32.u64 %0, t; }"
        : "=r"(a) : "l"(ptr));
    return a;
}
__device__ __forceinline__ float2 unpk(unsigned long long v) {
    uint32_t lo, hi;
    asm("mov.b64 {%0,%1}, %2;" : "=r"(lo), "=r"(hi) : "l"(v));
    return make_float2(__uint_as_float(lo), __uint_as_float(hi));
}
__device__ __forceinline__ unsigned long long dup2(float w) {
    unsigned long long d; uint32_t u = __float_as_uint(w);
    asm("mov.b64 %0, {%1,%1};" : "=l"(d) : "r"(u));
    return d;
}
#define FMA2(acc, a, b) \
    asm("fma.rn.f32x2 %0, %1, %2, %0;" : "+l"(acc) : "l"(a), "l"(b))
#define ADD2(d, s) \
    asm("add.rn.f32x2 %0, %0, %1;" : "+l"(d) : "l"(s))

// 8-row x 4-batch dot, rows packed in f32x2. lane=(ks=lane&7, bq=lane>>3).
template <int NITER>
__device__ __forceinline__ void dot8w(uint32_t za, uint32_t wa,
                                      int zstep, int wstep,
                                      unsigned long long acc[16]) {
#pragma unroll 4
    for (int i = 0; i < NITER; ++i) {
        unsigned long long w01, w23, w45, w67;
        asm volatile("ld.shared.v2.b64 {%0,%1}, [%2];"
                     : "=l"(w01), "=l"(w23) : "r"(wa));
        asm volatile("ld.shared.v2.b64 {%0,%1}, [%2];"
                     : "=l"(w45), "=l"(w67) : "r"(wa + 16));
        float z0, z1, z2, z3;
        asm volatile("ld.shared.v4.f32 {%0,%1,%2,%3}, [%4];"
                     : "=f"(z0), "=f"(z1), "=f"(z2), "=f"(z3) : "r"(za));
        unsigned long long d;
        d = dup2(z0);
        FMA2(acc[0],  w01, d); FMA2(acc[1],  w23, d);
        FMA2(acc[2],  w45, d); FMA2(acc[3],  w67, d);
        d = dup2(z1);
        FMA2(acc[4],  w01, d); FMA2(acc[5],  w23, d);
        FMA2(acc[6],  w45, d); FMA2(acc[7],  w67, d);
        d = dup2(z2);
        FMA2(acc[8],  w01, d); FMA2(acc[9],  w23, d);
        FMA2(acc[10], w45, d); FMA2(acc[11], w67, d);
        d = dup2(z3);
        FMA2(acc[12], w01, d); FMA2(acc[13], w23, d);
        FMA2(acc[14], w45, d); FMA2(acc[15], w67, d);
        za += zstep; wa += wstep;
    }
}

// shfl tree-reduce over ks (xor 4,2,1): v[b] = full dot for row oct*8+ks,
// batch bq*4+b.
__device__ __forceinline__ void kreduce8w(unsigned long long acc[16], int ks,
                                          float v[4]) {
    const bool b2 = (ks & 4) != 0;
    unsigned long long na[8];
#pragma unroll
    for (int b = 0; b < 4; ++b)
#pragma unroll
        for (int q = 0; q < 2; ++q) {
            unsigned long long kpt = b2 ? acc[b*4+2+q] : acc[b*4+q];
            unsigned long long snd = b2 ? acc[b*4+q]   : acc[b*4+2+q];
            unsigned long long rcv = __shfl_xor_sync(0xffffffffu, snd, 4);
            ADD2(kpt, rcv);
            na[b*2+q] = kpt;
        }
    const bool b1 = (ks & 2) != 0;
    unsigned long long nb[4];
#pragma unroll
    for (int b = 0; b < 4; ++b) {
        unsigned long long kpt = b1 ? na[b*2+1] : na[b*2+0];
        unsigned long long snd = b1 ? na[b*2+0] : na[b*2+1];
        unsigned long long rcv = __shfl_xor_sync(0xffffffffu, snd, 2);
        ADD2(kpt, rcv);
        nb[b] = kpt;
    }
    const bool b0 = (ks & 1) != 0;
#pragma unroll
    for (int b = 0; b < 4; ++b) {
        unsigned long long rcv = __shfl_xor_sync(0xffffffffu, nb[b], 1);
        ADD2(nb[b], rcv);
        float2 pq = unpk(nb[b]);
        v[b] = b0 ? pq.y : pq.x;
    }
}

__global__ void __launch_bounds__(NTHR, 1)
gru_att_persistent(const float* __restrict__ x,      // [B,S,I]
                   const float* __restrict__ hid,    // [B,H]
                   const float* __restrict__ W_att,  // [256,512]
                   const float* __restrict__ b_att,  // [256]
                   const float* __restrict__ w_ih,   // [768,256]
                   const float* __restrict__ b_ih,   // [768]
                   const float* __restrict__ w_hh,   // [768,256]
                   const float* __restrict__ b_hh,   // [768]
                   float* __restrict__ out)          // [B,S,H]
{
    extern __shared__ float smf[];
    const int tid  = threadIdx.x;
    const int g    = blockIdx.x & 15;
    const int p    = blockIdx.x >> 4;
    const int wid  = tid >> 5;
    const int lane = tid & 31;
    const int ks   = lane & 7;
    const int bq   = lane >> 3;
    const uint32_t smb = sm_u32(smf);
    unsigned* base_sm = (unsigned*)(smf + OFF_BASE);
    float* ghT  = g_hT  + p * 4096;   // [256][16]
    float* gxgT = g_xgT + p * 4096;

    if (tid < 16) base_sm[tid] = g_flag[(p * 16 + tid) * 32];

    // ---- stage weights (transposed, gate-triple row sets) ----
    for (int idx = tid; idx < 512 * 16; idx += NTHR) {
        int k = idx >> 4, rr = idx & 15;
        smf[OFF_W1 + k * W1STR + rr] = W_att[(g * 16 + rr) * 512 + k];
    }
    for (int idx = tid; idx < 256 * 48; idx += NTHR) {
        int k = idx / 48, rl = idx % 48;
        int gate = rl >> 4, jj = rl & 15;
        smf[OFF_W2 + k * W2STR + rl] = w_hh[(gate * 256 + g * 16 + jj) * 256 + k];
    }
    for (int idx = tid; idx < 256 * 48; idx += NTHR) {
        int k = idx / 48, rl = idx % 48;
        int gate = rl >> 4, jj = rl & 15;
        smf[OFF_WC + k * WCSTR + rl] = w_ih[(gate * 256 + g * 16 + jj) * 256 + k];
    }
    if (tid < 16) smf[OFF_BA + tid] = b_att[g * 16 + tid];
    if (tid < 48) {
        int gate = tid >> 4, jj = tid & 15;
        smf[OFF_BHH + tid] = b_hh[gate * 256 + g * 16 + jj];
        smf[OFF_BIH + tid] = b_ih[gate * 256 + g * 16 + jj];
    }

    // ---- init transposed hidden state (one writer block per batch group) ---
    if (g == 0) {
        for (int idx = tid; idx < 4096; idx += NTHR) {
            int k = idx >> 4, bb = idx & 15;
            ghT[idx] = hid[(p * 16 + bb) * 256 + k];
        }
    }
    // ---- own h-slice into zT ----
    if (tid < 256) {
        int bb = tid & 15, jj = tid >> 4;
        smf[OFF_Z + (256 + g * 16 + jj) * ZSTR + bb] =
            hid[(p * 16 + bb) * 256 + g * 16 + jj];
    }

    // ---- pre-loop: XN <- x(0); A1x(0) by warps 12-15 ----
    for (int idx = tid; idx < 1024; idx += NTHR) {
        int bb = idx & 15, q4 = idx >> 4;
        float4 v = *(const float4*)&x[((p * 16 + bb) * S_LEN + 0) * 256 + q4 * 4];
        int base = OFF_XN + (q4 * 4) * ZSTR + bb;
        smf[base] = v.x; smf[base + ZSTR] = v.y;
        smf[base + 2 * ZSTR] = v.z; smf[base + 3 * ZSTR] = v.w;
    }
    __syncthreads();
    if (wid >= 12) {
        const int a = wid - 12, oct = a >> 1, kh = a & 1;
        unsigned long long acc[16] = {0,0,0,0,0,0,0,0,0,0,0,0,0,0,0,0};
        uint32_t za = smb + (OFF_XN + (kh * 128 + ks) * ZSTR  + bq * 4) * 4;
        uint32_t wa = smb + (OFF_W1 + (kh * 128 + ks) * W1STR + oct * 8) * 4;
        dot8w<16>(za, wa, 8 * ZSTR * 4, 8 * W1STR * 4, acc);
        float v[4];
        kreduce8w(acc, ks, v);
        int r = oct * 8 + ks;
        *(float4*)&smf[OFF_PB1X + kh * (16 * PBS) + r * PBS + bq * 4] =
            make_float4(v[0], v[1], v[2], v[3]);
    }

    unsigned barn = 1;
    pbar_arrive(base_sm, g, barn);
    pbar_wait(base_sm, p, barn);

    for (int t = 0; t < S_LEN; ++t) {
        // ==== loop top: stage peer h slices + save own x(t) rows to XV ====
        for (int idx = tid; idx < 1024; idx += NTHR) {
            int i = idx >> 2, bb4 = (idx & 3) << 2;
            if ((i >> 4) != g) {
                float4 v = *(const float4*)&ghT[i * 16 + bb4];
                *(float4*)&smf[OFF_Z + (256 + i) * ZSTR + bb4] = v;
            }
        }
        if (tid < 256) {   // XV <- XN own rows (x(t)), before XN is reused
            int bb = tid & 15, rr = tid >> 4;
            smf[OFF_XV + rr * XVS + bb] =
                smf[OFF_XN + (g * 16 + rr) * ZSTR + bb];
        }
        __syncthreads();

        // ==== XN <- x(t+1): LDGs issue here, hidden under dot1 ====
        if (t + 1 < S_LEN) {
            for (int idx = tid; idx < 1024; idx += NTHR) {
                int bb = idx & 15, q4 = idx >> 4;
                float4 v = *(const float4*)
                    &x[((p * 16 + bb) * S_LEN + (t + 1)) * 256 + q4 * 4];
                int base = OFF_XN + (q4 * 4) * ZSTR + bb;
                smf[base] = v.x; smf[base + ZSTR] = v.y;
                smf[base + 2 * ZSTR] = v.z; smf[base + 3 * ZSTR] = v.w;
            }
        }

        // ==== dot1 (K=256 each): A1h warps 0-3, A2 warps 4-15 ====
        if (wid < 4) {
            const int oct = wid >> 1, kh = wid & 1;
            unsigned long long acc[16] = {0,0,0,0,0,0,0,0,0,0,0,0,0,0,0,0};
            uint32_t za = smb + (OFF_Z  + (256 + kh * 128 + ks) * ZSTR + bq * 4) * 4;
            uint32_t wa = smb + (OFF_W1 + (256 + kh * 128 + ks) * W1STR + oct * 8) * 4;
            dot8w<16>(za, wa, 8 * ZSTR * 4, 8 * W1STR * 4, acc);
            float v[4];
            kreduce8w(acc, ks, v);
            int r = oct * 8 + ks;
            *(float4*)&smf[OFF_PB1H + kh * (16 * PBS) + r * PBS + bq * 4] =
                make_float4(v[0], v[1], v[2], v[3]);
        } else {
            const int a2 = wid - 4, oct = a2 >> 1, kh = a2 & 1;
            unsigned long long acc[16] = {0,0,0,0,0,0,0,0,0,0,0,0,0,0,0,0};
            uint32_t za = smb + (OFF_Z  + (256 + kh * 128 + ks) * ZSTR + bq * 4) * 4;
            uint32_t wa = smb + (OFF_W2 + (kh * 128 + ks) * W2STR + oct * 8) * 4;
            dot8w<16>(za, wa, 8 * ZSTR * 4, 8 * W2STR * 4, acc);
            float v[4];
            kreduce8w(acc, ks, v);
            int r = oct * 8 + ks;
            *(float4*)&smf[OFF_PB2 + kh * (48 * PBS) + r * PBS + bq * 4] =
                make_float4(v[0], v[1], v[2], v[3]);
        }
        __syncthreads();

        // ---- xg = x(t)*sigmoid(A1x+A1h); xv from XV; STG + STS own slice ---
        if (tid < 256) {
            int bb = tid & 15, rr = tid >> 4;
            float s = smf[OFF_PB1H + rr * PBS + bb]
                    + smf[OFF_PB1H + 16 * PBS + rr * PBS + bb]
                    + smf[OFF_PB1X + rr * PBS + bb]
                    + smf[OFF_PB1X + 16 * PBS + rr * PBS + bb]
                    + smf[OFF_BA + rr];
            float a  = sigmoidf_(s);
            float xv = smf[OFF_XV + rr * XVS + bb];               // x(t)
            float val = xv * a;
            gxgT[(g * 16 + rr) * 16 + bb] = val;                  // coalesced
            smf[OFF_Z + (g * 16 + rr) * ZSTR + bb] = val;         // own slice
        }

        // ==== bar A: arrive -> wait (window empty; XN already in flight) ====
        ++barn;
        pbar_arrive(base_sm, g, barn);
        pbar_wait(base_sm, p, barn);

        // ---- stage peer xg slices (skip own) ----
        for (int idx = tid; idx < 1024; idx += NTHR) {
            int i = idx >> 2, bb4 = (idx & 3) << 2;
            if ((i >> 4) != g) {
                float4 v = *(const float4*)&gxgT[i * 16 + bb4];
                *(float4*)&smf[OFF_Z + i * ZSTR + bb4] = v;
            }
        }
        __syncthreads();

        // ==== C dot: warps 0-11 only ====
        if (wid < 12) {
            const int oct = wid >> 1, kh = wid & 1;
            unsigned long long acc[16] = {0,0,0,0,0,0,0,0,0,0,0,0,0,0,0,0};
            uint32_t za = smb + (OFF_Z  + (kh * 128 + ks) * ZSTR  + bq * 4) * 4;
            uint32_t wa = smb + (OFF_WC + (kh * 128 + ks) * WCSTR + oct * 8) * 4;
            dot8w<16>(za, wa, 8 * ZSTR * 4, 8 * WCSTR * 4, acc);
            float v[4];
            kreduce8w(acc, ks, v);
            int r = oct * 8 + ks;
            *(float4*)&smf[OFF_PBC + kh * (48 * PBS) + r * PBS + bq * 4] =
                make_float4(v[0], v[1], v[2], v[3]);
        }
        __syncthreads();

        // ---- epilogue: gates + h update; STG ghT coalesced + STS own zT ----
        if (tid < 256) {
            int bb = tid & 15, jj = tid >> 4;
            int j  = g * 16 + jj;
            float hp = smf[OFF_Z + (256 + j) * ZSTR + bb];
            float gi[3], gh_[3];
#pragma unroll
            for (int gate = 0; gate < 3; ++gate) {
                int r = gate * 16 + jj;
                gi[gate] = smf[OFF_PBC + r * PBS + bb]
                         + smf[OFF_PBC + 48 * PBS + r * PBS + bb]
                         + smf[OFF_BIH + r];
                gh_[gate] = smf[OFF_PB2 + r * PBS + bb]
                          + smf[OFF_PB2 + 48 * PBS + r * PBS + bb]
                          + smf[OFF_BHH + r];
            }
            float r_ = sigmoidf_(gi[0] + gh_[0]);
            float z_ = sigmoidf_(gi[1] + gh_[1]);
            float n_ = tanhf(gi[2] + r_ * gh_[2]);
            float hn = (1.0f - z_) * n_ + z_ * hp;
            ghT[j * 16 + bb] = hn;                        // coalesced STG
            smf[OFF_Z + (256 + j) * ZSTR + bb] = hn;      // own slice for t+1
        }

        // ==== bar B: arrive; window = out STG + A1x(t+1) ====
        ++barn;
        pbar_arrive(base_sm, g, barn);   // syncthreads: zT h-slice visible
        if (tid < 256) {                 // coalesced out write from zT
            int jj = tid & 15, bb = tid >> 4;
            float hv = smf[OFF_Z + (256 + g * 16 + jj) * ZSTR + bb];
            out[((p * 16 + bb) * S_LEN + t) * 256 + g * 16 + jj] = hv;
        } else if (wid >= 12 && t + 1 < S_LEN) {   // A1x(t+1) from XN
            const int a = wid - 12, oct = a >> 1, kh = a & 1;
            unsigned long long acc[16] = {0,0,0,0,0,0,0,0,0,0,0,0,0,0,0,0};
            uint32_t za = smb + (OFF_XN + (kh * 128 + ks) * ZSTR  + bq * 4) * 4;
            uint32_t wa = smb + (OFF_W1 + (kh * 128 + ks) * W1STR + oct * 8) * 4;
            dot8w<16>(za, wa, 8 * ZSTR * 4, 8 * W1STR * 4, acc);
            float v[4];
            kreduce8w(acc, ks, v);
            int r = oct * 8 + ks;
            *(float4*)&smf[OFF_PB1X + kh * (16 * PBS) + r * PBS + bq * 4] =
                make_float4(v[0], v[1], v[2], v[3]);
        }
        pbar_wait(base_sm, p, barn);     // h_new of all 16 CTAs visible
    }
}

extern "C" void kernel_launch(void* const* d_in, const int* in_sizes, int n_in,
                              void* d_out, int out_size) {
    const float* x     = (const float*)d_in[0];
    const float* hid   = (const float*)d_in[1];
    const float* W_att = (const float*)d_in[2];
    const float* b_att = (const float*)d_in[3];
    const float* w_ih  = (const float*)d_in[4];
    const float* b_ih  = (const float*)d_in[5];
    const float* w_hh  = (const float*)d_in[6];
    const float* b_hh  = (const float*)d_in[7];
    float* out = (float*)d_out;

    cudaFuncSetAttribute(gru_att_persistent,
                         cudaFuncAttributeMaxDynamicSharedMemorySize, SMEM_BYTES);

    gru_att_persistent<<<NBLK, NTHR, SMEM_BYTES>>>(
        x, hid, W_att, b_att, w_ih, b_ih, w_hh, b_hh, out);
}

// round 17
// speedup vs baseline: 1.1001x; 1.1001x over previous
#include <cuda_runtime.h>
#include <cstdint>

// ============================================================================
// GRU_Att_Layer R17: R13 exactly + streaming cache hints.
//  - x loads via __ldcs (read-once, evict-first), out stores via __stcs
//    -> keeps hot L2 lines (ghT/gxgT/flags) resident for barrier/exchange
//  - flag barriers, dot8w FFMA2 tiles, classic launch (R13 skeleton verbatim)
// B=128,S=1024,I=256,H=256. 128 CTAs: g=blockIdx&15 rows, p=blockIdx>>4.
// 512 threads.
// ============================================================================

#define S_LEN 1024
#define NBLK  128
#define NTHR  512

#define ZSTR  20
#define W1STR 20
#define W2STR 52
#define WCSTR 52
#define PBS   20

// SMEM layout (float offsets)
#define OFF_W1   0                        // [512][20] W_att^T (16 rows)
#define OFF_W2   (OFF_W1 + 512*W1STR)     // 10240 [256][52] w_hh^T triples
#define OFF_WC   (OFF_W2 + 256*W2STR)     // 23552 [256][52] w_ih^T triples
#define OFF_Z    (OFF_WC + 256*WCSTR)     // 36864 [512][20]: [xg ; h]^T
#define OFF_XN   (OFF_Z  + 512*ZSTR)      // 47104 [256][20] x(t or t+1)^T
#define OFF_PB2  (OFF_XN + 256*ZSTR)      // 52224 [2][48][20] gh partials
#define OFF_PB1H (OFF_PB2 + 2*48*PBS)     // 54144 [2][16][20]
#define OFF_PB1X (OFF_PB1H + 2*16*PBS)    // 54784 [2][16][20]
#define OFF_PBC  (OFF_PB1X + 2*16*PBS)    // 55424 [2][48][20]
#define OFF_BA   (OFF_PBC + 2*48*PBS)     // 57344
#define OFF_BHH  (OFF_BA + 16)
#define OFF_BIH  (OFF_BHH + 48)
#define OFF_BASE (OFF_BIH + 48)           // 57456: 16 flag bases
#define SMEM_FLOATS (OFF_BASE + 16)       // 57472
#define SMEM_BYTES  (SMEM_FLOATS * 4)     // 229888 B

// ---------------- scratch (device globals; allocation forbidden) -----------
// transposed: [pgroup][k 0..255][bb 0..15]
__device__ __align__(16) float g_hT [8 * 256 * 16];
__device__ __align__(16) float g_xgT[8 * 256 * 16];
__device__ unsigned g_flag[NBLK * 32];   // per-CTA epoch, own sector

// ---------------- split flag barrier: arrive / wait -------------------------
__device__ __forceinline__ void pbar_arrive(const unsigned* base_sm, int g,
                                            unsigned n) {
    __syncthreads();                       // CTA's phase stores issued
    if (threadIdx.x == 0) {
        __threadfence();                   // publish them
        *(volatile unsigned*)&g_flag[blockIdx.x * 32] = base_sm[g] + n;
    }
}
__device__ __forceinline__ void pbar_wait(const unsigned* base_sm, int p,
                                          unsigned n) {
    if (threadIdx.x < 16) {
        volatile unsigned* f = &g_flag[(p * 16 + threadIdx.x) * 32];
        unsigned tgt = base_sm[threadIdx.x] + n;
        while ((int)(*f - tgt) < 0) { }
        __threadfence();                   // acquire
    }
    __syncthreads();
}

__device__ __forceinline__ float sigmoidf_(float x) {
    return 1.0f / (1.0f + __expf(-x));
}
__device__ __forceinline__ uint32_t sm_u32(const void* ptr) {
    uint32_t a;
    asm("{ .reg .u64 t; cvta.to.shared.u64 t, %1; cvt.u32.u64 %0, t; }"
        : "=r"(a) : "l"(ptr));
    return a;
}
__device__ __forceinline__ float2 unpk(unsigned long long v) {
    uint32_t lo, hi;
    asm("mov.b64 {%0,%1}, %2;" : "=r"(lo), "=r"(hi) : "l"(v));
    return make_float2(__uint_as_float(lo), __uint_as_float(hi));
}
__device__ __forceinline__ unsigned long long dup2(float w) {
    unsigned long long d; uint32_t u = __float_as_uint(w);
    asm("mov.b64 %0, {%1,%1};" : "=l"(d) : "r"(u));
    return d;
}
#define FMA2(acc, a, b) \
    asm("fma.rn.f32x2 %0, %1, %2, %0;" : "+l"(acc) : "l"(a), "l"(b))
#define ADD2(d, s) \
    asm("add.rn.f32x2 %0, %0, %1;" : "+l"(d) : "l"(s))

// 8-row x 4-batch dot, rows packed in f32x2. lane=(ks=lane&7, bq=lane>>3).
template <int NITER>
__device__ __forceinline__ void dot8w(uint32_t za, uint32_t wa,
                                      int zstep, int wstep,
                                      unsigned long long acc[16]) {
#pragma unroll 4
    for (int i = 0; i < NITER; ++i) {
        unsigned long long w01, w23, w45, w67;
        asm volatile("ld.shared.v2.b64 {%0,%1}, [%2];"
                     : "=l"(w01), "=l"(w23) : "r"(wa));
        asm volatile("ld.shared.v2.b64 {%0,%1}, [%2];"
                     : "=l"(w45), "=l"(w67) : "r"(wa + 16));
        float z0, z1, z2, z3;
        asm volatile("ld.shared.v4.f32 {%0,%1,%2,%3}, [%4];"
                     : "=f"(z0), "=f"(z1), "=f"(z2), "=f"(z3) : "r"(za));
        unsigned long long d;
        d = dup2(z0);
        FMA2(acc[0],  w01, d); FMA2(acc[1],  w23, d);
        FMA2(acc[2],  w45, d); FMA2(acc[3],  w67, d);
        d = dup2(z1);
        FMA2(acc[4],  w01, d); FMA2(acc[5],  w23, d);
        FMA2(acc[6],  w45, d); FMA2(acc[7],  w67, d);
        d = dup2(z2);
        FMA2(acc[8],  w01, d); FMA2(acc[9],  w23, d);
        FMA2(acc[10], w45, d); FMA2(acc[11], w67, d);
        d = dup2(z3);
        FMA2(acc[12], w01, d); FMA2(acc[13], w23, d);
        FMA2(acc[14], w45, d); FMA2(acc[15], w67, d);
        za += zstep; wa += wstep;
    }
}

// shfl tree-reduce over ks (xor 4,2,1): v[b] = full dot for row oct*8+ks,
// batch bq*4+b.
__device__ __forceinline__ void kreduce8w(unsigned long long acc[16], int ks,
                                          float v[4]) {
    const bool b2 = (ks & 4) != 0;
    unsigned long long na[8];
#pragma unroll
    for (int b = 0; b < 4; ++b)
#pragma unroll
        for (int q = 0; q < 2; ++q) {
            unsigned long long kpt = b2 ? acc[b*4+2+q] : acc[b*4+q];
            unsigned long long snd = b2 ? acc[b*4+q]   : acc[b*4+2+q];
            unsigned long long rcv = __shfl_xor_sync(0xffffffffu, snd, 4);
            ADD2(kpt, rcv);
            na[b*2+q] = kpt;
        }
    const bool b1 = (ks & 2) != 0;
    unsigned long long nb[4];
#pragma unroll
    for (int b = 0; b < 4; ++b) {
        unsigned long long kpt = b1 ? na[b*2+1] : na[b*2+0];
        unsigned long long snd = b1 ? na[b*2+0] : na[b*2+1];
        unsigned long long rcv = __shfl_xor_sync(0xffffffffu, snd, 2);
        ADD2(kpt, rcv);
        nb[b] = kpt;
    }
    const bool b0 = (ks & 1) != 0;
#pragma unroll
    for (int b = 0; b < 4; ++b) {
        unsigned long long rcv = __shfl_xor_sync(0xffffffffu, nb[b], 1);
        ADD2(nb[b], rcv);
        float2 pq = unpk(nb[b]);
        v[b] = b0 ? pq.y : pq.x;
    }
}

__global__ void __launch_bounds__(NTHR, 1)
gru_att_persistent(const float* __restrict__ x,      // [B,S,I]
                   const float* __restrict__ hid,    // [B,H]
                   const float* __restrict__ W_att,  // [256,512]
                   const float* __restrict__ b_att,  // [256]
                   const float* __restrict__ w_ih,   // [768,256]
                   const float* __restrict__ b_ih,   // [768]
                   const float* __restrict__ w_hh,   // [768,256]
                   const float* __restrict__ b_hh,   // [768]
                   float* __restrict__ out)          // [B,S,H]
{
    extern __shared__ float smf[];
    const int tid  = threadIdx.x;
    const int g    = blockIdx.x & 15;
    const int p    = blockIdx.x >> 4;
    const int wid  = tid >> 5;
    const int lane = tid & 31;
    const int ks   = lane & 7;
    const int bq   = lane >> 3;
    const uint32_t smb = sm_u32(smf);
    unsigned* base_sm = (unsigned*)(smf + OFF_BASE);
    float* ghT  = g_hT  + p * 4096;   // [256][16]
    float* gxgT = g_xgT + p * 4096;

    if (tid < 16) base_sm[tid] = g_flag[(p * 16 + tid) * 32];

    // ---- stage weights (transposed, gate-triple row sets) ----
    for (int idx = tid; idx < 512 * 16; idx += NTHR) {
        int k = idx >> 4, rr = idx & 15;
        smf[OFF_W1 + k * W1STR + rr] = W_att[(g * 16 + rr) * 512 + k];
    }
    for (int idx = tid; idx < 256 * 48; idx += NTHR) {
        int k = idx / 48, rl = idx % 48;
        int gate = rl >> 4, jj = rl & 15;
        smf[OFF_W2 + k * W2STR + rl] = w_hh[(gate * 256 + g * 16 + jj) * 256 + k];
    }
    for (int idx = tid; idx < 256 * 48; idx += NTHR) {
        int k = idx / 48, rl = idx % 48;
        int gate = rl >> 4, jj = rl & 15;
        smf[OFF_WC + k * WCSTR + rl] = w_ih[(gate * 256 + g * 16 + jj) * 256 + k];
    }
    if (tid < 16) smf[OFF_BA + tid] = b_att[g * 16 + tid];
    if (tid < 48) {
        int gate = tid >> 4, jj = tid & 15;
        smf[OFF_BHH + tid] = b_hh[gate * 256 + g * 16 + jj];
        smf[OFF_BIH + tid] = b_ih[gate * 256 + g * 16 + jj];
    }

    // ---- init transposed hidden state (one writer block per batch group) ---
    if (g == 0) {
        for (int idx = tid; idx < 4096; idx += NTHR) {
            int k = idx >> 4, bb = idx & 15;
            ghT[idx] = hid[(p * 16 + bb) * 256 + k];
        }
    }
    // ---- own h-slice into zT ----
    if (tid < 256) {
        int bb = tid & 15, jj = tid >> 4;
        smf[OFF_Z + (256 + g * 16 + jj) * ZSTR + bb] =
            hid[(p * 16 + bb) * 256 + g * 16 + jj];
    }

    // ---- pre-loop: XN <- x(0) (streaming loads); A1x(0) by warps 12-15 ----
    for (int idx = tid; idx < 1024; idx += NTHR) {
        int bb = idx & 15, q4 = idx >> 4;
        float4 v = __ldcs((const float4*)
                          &x[((p * 16 + bb) * S_LEN + 0) * 256 + q4 * 4]);
        int base = OFF_XN + (q4 * 4) * ZSTR + bb;
        smf[base] = v.x; smf[base + ZSTR] = v.y;
        smf[base + 2 * ZSTR] = v.z; smf[base + 3 * ZSTR] = v.w;
    }
    __syncthreads();
    if (wid >= 12) {
        const int a = wid - 12, oct = a >> 1, kh = a & 1;
        unsigned long long acc[16] = {0,0,0,0,0,0,0,0,0,0,0,0,0,0,0,0};
        uint32_t za = smb + (OFF_XN + (kh * 128 + ks) * ZSTR  + bq * 4) * 4;
        uint32_t wa = smb + (OFF_W1 + (kh * 128 + ks) * W1STR + oct * 8) * 4;
        dot8w<16>(za, wa, 8 * ZSTR * 4, 8 * W1STR * 4, acc);
        float v[4];
        kreduce8w(acc, ks, v);
        int r = oct * 8 + ks;
        *(float4*)&smf[OFF_PB1X + kh * (16 * PBS) + r * PBS + bq * 4] =
            make_float4(v[0], v[1], v[2], v[3]);
    }

    unsigned barn = 1;
    pbar_arrive(base_sm, g, barn);
    pbar_wait(base_sm, p, barn);

    for (int t = 0; t < S_LEN; ++t) {
        // ==== prologue: stage peer h slices (128-bit ld/st, skip own) ====
        for (int idx = tid; idx < 1024; idx += NTHR) {
            int i = idx >> 2, bb4 = (idx & 3) << 2;
            if ((i >> 4) != g) {
                float4 v = *(const float4*)&ghT[i * 16 + bb4];
                *(float4*)&smf[OFF_Z + (256 + i) * ZSTR + bb4] = v;
            }
        }
        __syncthreads();

        // ==== dot1 (K=256 each): A1h warps 0-3, A2 warps 4-15 ====
        if (wid < 4) {
            const int oct = wid >> 1, kh = wid & 1;
            unsigned long long acc[16] = {0,0,0,0,0,0,0,0,0,0,0,0,0,0,0,0};
            uint32_t za = smb + (OFF_Z  + (256 + kh * 128 + ks) * ZSTR + bq * 4) * 4;
            uint32_t wa = smb + (OFF_W1 + (256 + kh * 128 + ks) * W1STR + oct * 8) * 4;
            dot8w<16>(za, wa, 8 * ZSTR * 4, 8 * W1STR * 4, acc);
            float v[4];
            kreduce8w(acc, ks, v);
            int r = oct * 8 + ks;
            *(float4*)&smf[OFF_PB1H + kh * (16 * PBS) + r * PBS + bq * 4] =
                make_float4(v[0], v[1], v[2], v[3]);
        } else {
            const int a2 = wid - 4, oct = a2 >> 1, kh = a2 & 1;
            unsigned long long acc[16] = {0,0,0,0,0,0,0,0,0,0,0,0,0,0,0,0};
            uint32_t za = smb + (OFF_Z  + (256 + kh * 128 + ks) * ZSTR + bq * 4) * 4;
            uint32_t wa = smb + (OFF_W2 + (kh * 128 + ks) * W2STR + oct * 8) * 4;
            dot8w<16>(za, wa, 8 * ZSTR * 4, 8 * W2STR * 4, acc);
            float v[4];
            kreduce8w(acc, ks, v);
            int r = oct * 8 + ks;
            *(float4*)&smf[OFF_PB2 + kh * (48 * PBS) + r * PBS + bq * 4] =
                make_float4(v[0], v[1], v[2], v[3]);
        }
        __syncthreads();

        // ---- xg = x(t)*sigmoid(A1x+A1h); STG transposed + STS own slice ----
        if (tid < 256) {
            int bb = tid & 15, rr = tid >> 4;
            float s = smf[OFF_PB1H + rr * PBS + bb]
                    + smf[OFF_PB1H + 16 * PBS + rr * PBS + bb]
                    + smf[OFF_PB1X + rr * PBS + bb]
                    + smf[OFF_PB1X + 16 * PBS + rr * PBS + bb]
                    + smf[OFF_BA + rr];
            float a  = sigmoidf_(s);
            float xv = smf[OFF_XN + (g * 16 + rr) * ZSTR + bb];   // x(t)
            float val = xv * a;
            gxgT[(g * 16 + rr) * 16 + bb] = val;                  // coalesced
            smf[OFF_Z + (g * 16 + rr) * ZSTR + bb] = val;         // own slice
        }

        // ==== bar A: arrive, stage XN <- x(t+1) in the window, wait ====
        ++barn;
        pbar_arrive(base_sm, g, barn);
        if (t + 1 < S_LEN) {
            for (int idx = tid; idx < 1024; idx += NTHR) {
                int bb = idx & 15, q4 = idx >> 4;
                float4 v = __ldcs((const float4*)
                    &x[((p * 16 + bb) * S_LEN + (t + 1)) * 256 + q4 * 4]);
                int base = OFF_XN + (q4 * 4) * ZSTR + bb;
                smf[base] = v.x; smf[base + ZSTR] = v.y;
                smf[base + 2 * ZSTR] = v.z; smf[base + 3 * ZSTR] = v.w;
            }
        }
        pbar_wait(base_sm, p, barn);

        // ---- stage peer xg slices (skip own) ----
        for (int idx = tid; idx < 1024; idx += NTHR) {
            int i = idx >> 2, bb4 = (idx & 3) << 2;
            if ((i >> 4) != g) {
                float4 v = *(const float4*)&gxgT[i * 16 + bb4];
                *(float4*)&smf[OFF_Z + i * ZSTR + bb4] = v;
            }
        }
        __syncthreads();

        // ==== C dot: warps 0-11 only ====
        if (wid < 12) {
            const int oct = wid >> 1, kh = wid & 1;
            unsigned long long acc[16] = {0,0,0,0,0,0,0,0,0,0,0,0,0,0,0,0};
            uint32_t za = smb + (OFF_Z  + (kh * 128 + ks) * ZSTR  + bq * 4) * 4;
            uint32_t wa = smb + (OFF_WC + (kh * 128 + ks) * WCSTR + oct * 8) * 4;
            dot8w<16>(za, wa, 8 * ZSTR * 4, 8 * WCSTR * 4, acc);
            float v[4];
            kreduce8w(acc, ks, v);
            int r = oct * 8 + ks;
            *(float4*)&smf[OFF_PBC + kh * (48 * PBS) + r * PBS + bq * 4] =
                make_float4(v[0], v[1], v[2], v[3]);
        }
        __syncthreads();

        // ---- epilogue: gates + h update; STG ghT coalesced + STS own zT ----
        if (tid < 256) {
            int bb = tid & 15, jj = tid >> 4;
            int j  = g * 16 + jj;
            float hp = smf[OFF_Z + (256 + j) * ZSTR + bb];
            float gi[3], gh_[3];
#pragma unroll
            for (int gate = 0; gate < 3; ++gate) {
                int r = gate * 16 + jj;
                gi[gate] = smf[OFF_PBC + r * PBS + bb]
                         + smf[OFF_PBC + 48 * PBS + r * PBS + bb]
                         + smf[OFF_BIH + r];
                gh_[gate] = smf[OFF_PB2 + r * PBS + bb]
                          + smf[OFF_PB2 + 48 * PBS + r * PBS + bb]
                          + smf[OFF_BHH + r];
            }
            float r_ = sigmoidf_(gi[0] + gh_[0]);
            float z_ = sigmoidf_(gi[1] + gh_[1]);
            float n_ = tanhf(gi[2] + r_ * gh_[2]);
            float hn = (1.0f - z_) * n_ + z_ * hp;
            ghT[j * 16 + bb] = hn;                        // coalesced STG
            smf[OFF_Z + (256 + j) * ZSTR + bb] = hn;      // own slice for t+1
        }

        // ==== bar B: arrive; window = out STG (streaming) + A1x(t+1) ====
        ++barn;
        pbar_arrive(base_sm, g, barn);   // syncthreads: zT h-slice visible
        if (tid < 256) {                 // coalesced streaming out write
            int jj = tid & 15, bb = tid >> 4;
            float hv = smf[OFF_Z + (256 + g * 16 + jj) * ZSTR + bb];
            __stcs(&out[((p * 16 + bb) * S_LEN + t) * 256 + g * 16 + jj], hv);
        } else if (wid >= 12 && t + 1 < S_LEN) {   // A1x(t+1) from XN
            const int a = wid - 12, oct = a >> 1, kh = a & 1;
            unsigned long long acc[16] = {0,0,0,0,0,0,0,0,0,0,0,0,0,0,0,0};
            uint32_t za = smb + (OFF_XN + (kh * 128 + ks) * ZSTR  + bq * 4) * 4;
            uint32_t wa = smb + (OFF_W1 + (kh * 128 + ks) * W1STR + oct * 8) * 4;
            dot8w<16>(za, wa, 8 * ZSTR * 4, 8 * W1STR * 4, acc);
            float v[4];
            kreduce8w(acc, ks, v);
            int r = oct * 8 + ks;
            *(float4*)&smf[OFF_PB1X + kh * (16 * PBS) + r * PBS + bq * 4] =
                make_float4(v[0], v[1], v[2], v[3]);
        }
        pbar_wait(base_sm, p, barn);     // h_new of all 16 CTAs visible
    }
}

extern "C" void kernel_launch(void* const* d_in, const int* in_sizes, int n_in,
                              void* d_out, int out_size) {
    const float* x     = (const float*)d_in[0];
    const float* hid   = (const float*)d_in[1];
    const float* W_att = (const float*)d_in[2];
    const float* b_att = (const float*)d_in[3];
    const float* w_ih  = (const float*)d_in[4];
    const float* b_ih  = (const float*)d_in[5];
    const float* w_hh  = (const float*)d_in[6];
    const float* b_hh  = (const float*)d_in[7];
    float* out = (float*)d_out;

    cudaFuncSetAttribute(gru_att_persistent,
                         cudaFuncAttributeMaxDynamicSharedMemorySize, SMEM_BYTES);

    gru_att_persistent<<<NBLK, NTHR, SMEM_BYTES>>>(
        x, hid, W_att, b_att, w_ih, b_ih, w_hh, b_hh, out);
}